// round 8
// baseline (speedup 1.0000x reference)
#include <cuda_runtime.h>
#include <mma.h>
using namespace nvcuda;

#define N_NODES 50000
#define N_PAD   50048          // multiple of 128
#define N_EDGES 400000

// ---------------- device scratch (no allocations allowed) ----------------
__device__ float g_bufA[(size_t)N_PAD * 512];
__device__ float g_bufB[(size_t)N_PAD * 512];
__device__ float g_el[N_NODES * 8];
__device__ float g_er[N_NODES * 8];
__device__ float g_W3[512 * 128];
__device__ int   g_rowptr[N_NODES + 1];
__device__ int   g_cursor[N_NODES];
__device__ int   g_eadj[N_EDGES];

__device__ __forceinline__ float lrelu(float x) { return x > 0.f ? x : 0.2f * x; }

// ---------------- CSR build (once per launch) ----------------
__global__ void count_kernel(const int* __restrict__ dst) {
    int e = blockIdx.x * blockDim.x + threadIdx.x;
    if (e < N_EDGES) atomicAdd(&g_cursor[dst[e]], 1);
}

__global__ void scan_kernel() {
    __shared__ int sh[1024];
    __shared__ int s_carry;
    if (threadIdx.x == 0) s_carry = 0;
    __syncthreads();
    for (int base = 0; base < N_NODES; base += 1024) {
        int i = base + threadIdx.x;
        int v = (i < N_NODES) ? g_cursor[i] : 0;
        sh[threadIdx.x] = v;
        __syncthreads();
        #pragma unroll
        for (int off = 1; off < 1024; off <<= 1) {
            int t = (threadIdx.x >= off) ? sh[threadIdx.x - off] : 0;
            __syncthreads();
            sh[threadIdx.x] += t;
            __syncthreads();
        }
        int excl = s_carry + sh[threadIdx.x] - v;
        if (i < N_NODES) { g_rowptr[i] = excl; g_cursor[i] = excl; }
        int total = sh[1023];
        __syncthreads();
        if (threadIdx.x == 0) s_carry += total;
        __syncthreads();
    }
    if (threadIdx.x == 0) g_rowptr[N_NODES] = s_carry;
}

__global__ void scatter_kernel(const int* __restrict__ src, const int* __restrict__ dst) {
    int e = blockIdx.x * blockDim.x + threadIdx.x;
    if (e < N_EDGES) {
        int p = atomicAdd(&g_cursor[dst[e]], 1);
        g_eadj[p] = src[e];
    }
}

// ---------------- W3 pad [512,40] -> [512,128] ----------------
__global__ void padW3_kernel(const float* __restrict__ W3) {
    int i = blockIdx.x * blockDim.x + threadIdx.x;
    if (i < 512 * 128) {
        int r = i >> 7, c = i & 127;
        g_W3[i] = (c < 40) ? W3[r * 40 + c] : 0.f;
    }
}

// ---------------- cp.async helpers ----------------
__device__ __forceinline__ void cp16(void* smem_dst, const void* gmem_src) {
    unsigned s = (unsigned)__cvta_generic_to_shared(smem_dst);
    asm volatile("cp.async.cg.shared.global [%0], [%1], 16;\n" :: "r"(s), "l"(gmem_src));
}
__device__ __forceinline__ void cp_commit() {
    asm volatile("cp.async.commit_group;\n");
}
template <int N>
__device__ __forceinline__ void cp_wait() {
    asm volatile("cp.async.wait_group %0;\n" :: "n"(N));
}

// ---------------- tf32 WMMA GEMM, double-buffered, 512 threads, 2 CTAs/SM ----------------
// block tile 128x128, k-tile 32; 16 warps, each 32x32 output (2x2 wmma frags)
#define LDA_S 40
#define LDB_S 136
#define A_STG (128 * LDA_S)
#define B_STG (32 * LDB_S)
#define SMEM_BYTES ((2 * A_STG + 2 * B_STG) * (int)sizeof(float))

__global__ __launch_bounds__(512, 2)
void wgemm_kernel(const float* __restrict__ A, const float* __restrict__ B,
                  float* __restrict__ C, int K, int M) {
    extern __shared__ float smem[];
    float* AsBase = smem;
    float* BsBase = smem + 2 * A_STG;

    const int t = threadIdx.x;
    const int wid = t >> 5;
    const int wr = wid & 3;        // warp row: rows 32*wr
    const int wc = wid >> 2;       // warp col: cols 32*wc
    const int rowBase = blockIdx.y * 128;
    const int colBase = blockIdx.x * 128;

    wmma::fragment<wmma::accumulator, 16, 16, 8, float> c[2][2];
    #pragma unroll
    for (int i = 0; i < 2; i++)
        #pragma unroll
        for (int j = 0; j < 2; j++) wmma::fill_fragment(c[i][j], 0.f);

    auto load_tiles = [&](int st, int k0) {
        float* As = AsBase + st * A_STG;
        float* Bs = BsBase + st * B_STG;
        #pragma unroll
        for (int i = 0; i < 2; i++) {            // A: 128x32 = 1024 float4
            int j = t + 512 * i;
            int row = j >> 3, c4 = j & 7;
            cp16(As + row * LDA_S + 4 * c4,
                 A + (size_t)(rowBase + row) * K + k0 + 4 * c4);
        }
        #pragma unroll
        for (int i = 0; i < 2; i++) {            // B: 32x128 = 1024 float4
            int j = t + 512 * i;
            int row = j >> 5, c4 = j & 31;
            cp16(Bs + row * LDB_S + 4 * c4,
                 B + (size_t)(k0 + row) * M + colBase + 4 * c4);
        }
        cp_commit();
    };

    const int KT = K / 32;
    load_tiles(0, 0);

    for (int kt = 0; kt < KT; kt++) {
        if (kt + 1 < KT) { load_tiles((kt + 1) & 1, (kt + 1) * 32); cp_wait<1>(); }
        else             { cp_wait<0>(); }
        __syncthreads();

        const float* As = AsBase + (kt & 1) * A_STG;
        const float* Bs = BsBase + (kt & 1) * B_STG;
        #pragma unroll
        for (int kk = 0; kk < 32; kk += 8) {
            wmma::fragment<wmma::matrix_a, 16, 16, 8, wmma::precision::tf32, wmma::row_major> a[2];
            wmma::fragment<wmma::matrix_b, 16, 16, 8, wmma::precision::tf32, wmma::row_major> b[2];
            #pragma unroll
            for (int i = 0; i < 2; i++) {
                wmma::load_matrix_sync(a[i], As + (wr * 32 + 16 * i) * LDA_S + kk, LDA_S);
                #pragma unroll
                for (int x = 0; x < a[i].num_elements; x++)
                    a[i].x[x] = wmma::__float_to_tf32(a[i].x[x]);
            }
            #pragma unroll
            for (int j = 0; j < 2; j++) {
                wmma::load_matrix_sync(b[j], Bs + kk * LDB_S + wc * 32 + 16 * j, LDB_S);
                #pragma unroll
                for (int x = 0; x < b[j].num_elements; x++)
                    b[j].x[x] = wmma::__float_to_tf32(b[j].x[x]);
            }
            #pragma unroll
            for (int i = 0; i < 2; i++)
                #pragma unroll
                for (int j = 0; j < 2; j++)
                    wmma::mma_sync(c[i][j], a[i], b[j], c[i][j]);
        }
        __syncthreads();
    }

    #pragma unroll
    for (int i = 0; i < 2; i++)
        #pragma unroll
        for (int j = 0; j < 2; j++)
            wmma::store_matrix_sync(
                C + (size_t)(rowBase + wr * 32 + 16 * i) * M + colBase + wc * 32 + 16 * j,
                c[i][j], M, wmma::mem_row_major);
}

// ---------------- per-node attention scores el/er (warp per node-head, float2) ----------------
template <int H, int D>
__global__ void scores_kernel(const float* __restrict__ feat,
                              const float* __restrict__ al,
                              const float* __restrict__ ar, int ldf) {
    static_assert(D <= 64, "one float2 per lane");
    int g = (blockIdx.x * blockDim.x + threadIdx.x) >> 5;
    int lane = threadIdx.x & 31;
    if (g >= N_NODES * H) return;
    int n = g / H, h = g % H;
    int ci = 2 * lane;
    float sl = 0.f, sr = 0.f;
    if (ci < D) {
        float2 v = *reinterpret_cast<const float2*>(feat + (size_t)n * ldf + h * D + ci);
        float2 a = *reinterpret_cast<const float2*>(al + h * D + ci);
        float2 b = *reinterpret_cast<const float2*>(ar + h * D + ci);
        sl = v.x * a.x + v.y * a.y;
        sr = v.x * b.x + v.y * b.y;
    }
    #pragma unroll
    for (int off = 16; off; off >>= 1) {
        sl += __shfl_down_sync(0xffffffffu, sl, off);
        sr += __shfl_down_sync(0xffffffffu, sr, off);
    }
    if (lane == 0) { g_el[n * H + h] = sl; g_er[n * H + h] = sr; }
}

// ---------------- fused softmax + aggregation: warp per node, tile per head ----------------
template <int H, int D>
__global__ void agg_kernel(const float* __restrict__ feat,
                           float* __restrict__ out, int ldf, int ostride) {
    static_assert(D <= 64, "one float2 per lane");
    int n = (blockIdx.x * blockDim.x + threadIdx.x) >> 5;
    int lane = threadIdx.x & 31;
    if (n >= N_NODES) return;
    const int h = blockIdx.y;
    int beg = g_rowptr[n], end = g_rowptr[n + 1];
    float er_h = g_er[n * H + h];

    // pass 1: denom, lane-per-edge
    float part = 0.f;
    for (int j = beg + lane; j < end; j += 32) {
        int s = g_eadj[j];
        part += __expf(lrelu(g_el[s * H + h] + er_h));
    }
    #pragma unroll
    for (int off = 16; off; off >>= 1)
        part += __shfl_xor_sync(0xffffffffu, part, off);
    float inv = (part > 0.f) ? 1.f / part : 0.f;

    // pass 2: weighted gather, lane-per-2-columns
    int ci = 2 * lane;
    bool ok = (ci < D);
    float2 acc = make_float2(0.f, 0.f);
    for (int j = beg; j < end; ++j) {
        int s = g_eadj[j];
        float a = __expf(lrelu(g_el[s * H + h] + er_h)) * inv;
        if (ok) {
            float2 f = *reinterpret_cast<const float2*>(
                feat + (size_t)s * ldf + h * D + ci);
            acc.x = fmaf(a, f.x, acc.x);
            acc.y = fmaf(a, f.y, acc.y);
        }
    }
    if (ok)
        *reinterpret_cast<float2*>(out + (size_t)n * ostride + h * D + ci) = acc;
}

// ---------------- launch ----------------
extern "C" void kernel_launch(void* const* d_in, const int* in_sizes, int n_in,
                              void* d_out, int out_size) {
    const float* features = (const float*)d_in[0];
    const int*   src      = (const int*)d_in[1];
    const int*   dst      = (const int*)d_in[2];
    const float* W1  = (const float*)d_in[3];
    const float* al1 = (const float*)d_in[4];
    const float* ar1 = (const float*)d_in[5];
    const float* W2  = (const float*)d_in[6];
    const float* al2 = (const float*)d_in[7];
    const float* ar2 = (const float*)d_in[8];
    const float* W3  = (const float*)d_in[9];
    const float* al3 = (const float*)d_in[10];
    const float* ar3 = (const float*)d_in[11];
    float* out = (float*)d_out;

    float *bufA, *bufB, *w3p; int* cur;
    cudaGetSymbolAddress((void**)&bufA, g_bufA);
    cudaGetSymbolAddress((void**)&bufB, g_bufB);
    cudaGetSymbolAddress((void**)&w3p,  g_W3);
    cudaGetSymbolAddress((void**)&cur,  g_cursor);

    cudaFuncSetAttribute(wgemm_kernel,
                         cudaFuncAttributeMaxDynamicSharedMemorySize, SMEM_BYTES);

    const int EB  = (N_EDGES + 255) / 256;
    const int NWB = (N_NODES * 32 + 255) / 256;   // warp per node

    // ---- CSR build (once; reused by all 3 layers) ----
    cudaMemsetAsync(cur, 0, N_NODES * sizeof(int));
    count_kernel<<<EB, 256>>>(dst);
    scan_kernel<<<1, 1024>>>();
    scatter_kernel<<<EB, 256>>>(src, dst);

    cudaMemcpyAsync(bufA, features, (size_t)N_NODES * 256 * sizeof(float),
                    cudaMemcpyDeviceToDevice);

    // ---- layer 1: 256 -> 8x64 ----
    wgemm_kernel<<<dim3(4, N_PAD / 128), 512, SMEM_BYTES>>>(bufA, W1, bufB, 256, 512);
    scores_kernel<8, 64><<<N_NODES, 256>>>(bufB, al1, ar1, 512);
    agg_kernel<8, 64><<<dim3(NWB, 8), 256>>>(bufB, bufA, 512, 512);

    // ---- layer 2: 8x64 -> 8x64 ----
    wgemm_kernel<<<dim3(4, N_PAD / 128), 512, SMEM_BYTES>>>(bufA, W2, bufB, 512, 512);
    scores_kernel<8, 64><<<N_NODES, 256>>>(bufB, al2, ar2, 512);
    agg_kernel<8, 64><<<dim3(NWB, 8), 256>>>(bufB, bufA, 512, 512);

    // ---- layer 3: 8x64 -> 40 (padded to 128 cols) ----
    padW3_kernel<<<(512 * 128 + 255) / 256, 256>>>(W3);
    wgemm_kernel<<<dim3(1, N_PAD / 128), 512, SMEM_BYTES>>>(bufA, w3p, bufB, 512, 128);
    scores_kernel<1, 40><<<(N_NODES + 7) / 8, 256>>>(bufB, al3, ar3, 128);
    agg_kernel<1, 40><<<dim3(NWB, 1), 256>>>(bufB, out, 128, 40);
}